// round 12
// baseline (speedup 1.0000x reference)
#include <cuda_runtime.h>
#include <math.h>
#include <math_constants.h>

#define THREADS 256
#define NBUCKET 32
#define MAXB 32768
#define MAXG 1024
#define MAXROWS 80

__device__ float g_part[MAXG][32];   // per-block partials: [0..15] soft, [16..31] hard
__device__ int   g_ctr = 0;

// ---- fallback-path globals ----
__device__ float g_acc[NBUCKET][64];

__global__ void init_acc_kernel() {
    g_acc[blockIdx.x][threadIdx.x] = 0.f;
}

__global__ void finalize_kernel(float* __restrict__ out_tail, float invB, int E) {
    int t = threadIdx.x;
    if (t < 2 * E) {
        int idx = (t < E) ? t : (32 + (t - E));
        float s = 0.f;
        #pragma unroll
        for (int b = 0; b < NBUCKET; b++) s += g_acc[b][idx];
        out_tail[t] = s * invB;
    }
}

// ---------------------------------------------------------------------------
// Single fused persistent kernel. E==16, DIN%32==0, DIN<=512, D%64==0.
// 6 CTAs/SM: reg budget 42 -> stream uses two a[4] half-batches.
// ---------------------------------------------------------------------------
__global__ __launch_bounds__(THREADS, 6) void moe16_kernel(
    const float* __restrict__ f, const float* __restrict__ x,
    const float* __restrict__ perm, const float* __restrict__ gate,
    const float* __restrict__ bias, float* __restrict__ y,
    int B, int D, int DIN, int P, int do_tail)
{
    constexpr int E = 16;
    __shared__ float gs[E * 513];
    __shared__ float pw[E * E];
    __shared__ float bs[E];
    __shared__ float sgp[MAXROWS * 16];
    __shared__ float part[8][32];
    __shared__ int   last_flag;

    const int tid    = threadIdx.x;
    const int lane   = tid & 31;
    const int warpId = tid >> 5;
    const int G      = gridDim.x;
    const int nK     = DIN >> 5;

    // ---- Phase 0: stage gate / pw / bias ----
    for (int i = tid; i < E * DIN; i += THREADS) {
        int e = i / DIN, k = i - e * DIN;
        gs[e * 513 + k] = gate[i];
    }
    const float invP = 1.f / (float)P;
    for (int i = tid; i < E * E; i += THREADS) {
        float s = 0.f;
        for (int p = 0; p < P; p++) s += perm[p * E * E + i];
        pw[i] = s * invP;
    }
    if (tid < E) bs[tid] = bias[tid];
    __syncthreads();

    // ---- Phase 1: gate this block's rows (warp per row) ----
    float partial = 0.f;
    for (int idx = warpId, b = blockIdx.x + warpId * G; b < B; idx += 8, b += 8 * G) {
        const float* xr = x + (size_t)b * DIN;
        float acc[E];
        #pragma unroll
        for (int e = 0; e < E; e++) acc[e] = 0.f;

        #pragma unroll 2
        for (int i = 0; i < nK; i++) {
            const int k = lane + (i << 5);
            const float xv = xr[k];
            const float* gcol = gs + k;
            #pragma unroll
            for (int e = 0; e < E; e++) acc[e] += xv * gcol[e * 513];
        }
        #pragma unroll
        for (int off = 16; off > 0; off >>= 1) {
            #pragma unroll
            for (int e = 0; e < E; e++)
                acc[e] += __shfl_xor_sync(0xffffffffu, acc[e], off);
        }
        #pragma unroll
        for (int e = 0; e < E; e++) acc[e] += bs[e];

        float v1 = -CUDART_INF_F; int i1 = 0;
        #pragma unroll
        for (int i = 0; i < E; i++) if (acc[i] > v1) { v1 = acc[i]; i1 = i; }
        float v2 = -CUDART_INF_F; int i2 = 0;
        #pragma unroll
        for (int i = 0; i < E; i++) if (i != i1 && acc[i] > v2) { v2 = acc[i]; i2 = i; }
        float m1 = (v1 == 0.f) ? -CUDART_INF_F : v1;
        float m2 = (v2 == 0.f) ? -CUDART_INF_F : v2;
        float m  = fmaxf(m1, m2);
        float e1 = __expf(m1 - m), e2 = __expf(m2 - m);
        float zi = 1.f / (e1 + e2);
        float g1 = e1 * zi, g2 = e2 * zi;
        float raw[E]; float s = 0.f;
        #pragma unroll
        for (int q = 0; q < E; q++) {
            raw[q] = g1 * pw[i1 * E + q] + g2 * pw[i2 * E + q];
            s += raw[q];
        }
        const float rinv = 1.f / s;

        const float val = raw[lane & 15] * rinv;
        if (lane < 16) {
            sgp[idx * 16 + lane] = val;
            partial += val;
        } else {
            partial += (val < 1e-5f) ? 0.f : 1.f;
        }
    }
    part[warpId][lane] = partial;
    __syncthreads();
    if (tid < 32) {
        float s = 0.f;
        #pragma unroll
        for (int w = 0; w < 8; w++) s += part[w][tid];
        g_part[blockIdx.x][tid] = s;
    }

    // ---- Phase 2: stream rows. Quad-per-d contiguous loads (4 wf/instr),
    //      two a[4] half-batches per row (16 data regs, MLP 4; depth from warps).
    const int dPerWarp = D >> 3;
    for (int idx = 0, b = blockIdx.x; b < B; idx++, b += G) {
        const float4 wsel = ((const float4*)(sgp + idx * 16))[lane & 3];
        const float4* fw = (const float4*)(f + (size_t)b * D * E)
                           + (size_t)warpId * (D >> 1);
        float* yr = y + (size_t)b * D + warpId * dPerWarp;
        const int outLane = lane >> 2;
        const bool qlead = (lane & 3) == 0;

        if (D == 512) {
            #pragma unroll
            for (int h = 0; h < 2; h++) {
                float4 a[4];
                #pragma unroll
                for (int j = 0; j < 4; j++) a[j] = fw[(h * 4 + j) * 32 + lane];
                #pragma unroll
                for (int j = 0; j < 4; j++) {
                    float p = a[j].x * wsel.x + a[j].y * wsel.y
                            + a[j].z * wsel.z + a[j].w * wsel.w;
                    p += __shfl_xor_sync(0xffffffffu, p, 1);
                    p += __shfl_xor_sync(0xffffffffu, p, 2);
                    if (qlead) yr[(h * 4 + j) * 8 + outLane] = p;
                }
            }
        } else {
            const int nJ = dPerWarp >> 3;
            #pragma unroll 4
            for (int j = 0; j < nJ; j++) {
                float4 a = fw[j * 32 + lane];
                float p = a.x * wsel.x + a.y * wsel.y + a.z * wsel.z + a.w * wsel.w;
                p += __shfl_xor_sync(0xffffffffu, p, 1);
                p += __shfl_xor_sync(0xffffffffu, p, 2);
                if (qlead) yr[j * 8 + outLane] = p;
            }
        }
    }

    // ---- Phase 3: last block reduces partials, writes tail ----
    __syncthreads();
    if (tid == 0) {
        __threadfence();
        int old = atomicAdd(&g_ctr, 1);
        last_flag = (old == G - 1) ? 1 : 0;
    }
    __syncthreads();
    if (last_flag) {
        __threadfence();
        float s = 0.f;
        for (int i = warpId; i < G; i += 8) s += g_part[i][lane];
        part[warpId][lane] = s;
        __syncthreads();
        if (tid < 32) {
            float tot = 0.f;
            #pragma unroll
            for (int w = 0; w < 8; w++) tot += part[w][tid];
            if (do_tail)
                y[(size_t)B * D + tid] = tot / (float)B;
        }
        if (tid == 0) g_ctr = 0;
    }
}

// ---------------------------------------------------------------------------
// Generic fallback (any E <= 32)
// ---------------------------------------------------------------------------
__global__ void fused_generic_kernel(
    const float* __restrict__ f, const float* __restrict__ x,
    const float* __restrict__ perm, const float* __restrict__ gate,
    const float* __restrict__ bias, float* __restrict__ y,
    int D, int DIN, int P, int E)
{
    extern __shared__ float smem[];
    float* xs     = smem;
    float* pw     = xs + DIN;
    float* logits = pw + E * E;
    float* gp     = logits + E;
    const int tid = threadIdx.x;
    const int b   = blockIdx.x;

    for (int k = tid; k < DIN; k += blockDim.x) xs[k] = x[(size_t)b * DIN + k];
    const float invP = 1.f / (float)P;
    for (int i = tid; i < E * E; i += blockDim.x) {
        float s = 0.f;
        for (int p = 0; p < P; p++) s += perm[p * E * E + i];
        pw[i] = s * invP;
    }
    __syncthreads();
    for (int e = tid; e < E; e += blockDim.x) {
        float s = 0.f;
        const float* gr = gate + (size_t)e * DIN;
        for (int k = 0; k < DIN; k++) s += xs[k] * gr[k];
        logits[e] = s + bias[e];
    }
    __syncthreads();
    if (tid == 0) {
        float v1 = -CUDART_INF_F; int i1 = 0;
        for (int i = 0; i < E; i++) if (logits[i] > v1) { v1 = logits[i]; i1 = i; }
        float v2 = -CUDART_INF_F; int i2 = 0;
        for (int i = 0; i < E; i++) if (i != i1 && logits[i] > v2) { v2 = logits[i]; i2 = i; }
        float m1 = (v1 == 0.f) ? -CUDART_INF_F : v1;
        float m2 = (v2 == 0.f) ? -CUDART_INF_F : v2;
        float m  = fmaxf(m1, m2);
        float e1 = __expf(m1 - m), e2 = __expf(m2 - m);
        float zi = 1.f / (e1 + e2);
        float g1 = e1 * zi, g2 = e2 * zi;
        float s = 0.f;
        for (int q = 0; q < E; q++) {
            float r = g1 * pw[i1 * E + q] + g2 * pw[i2 * E + q];
            gp[q] = r; s += r;
        }
        const float rinv = 1.f / s;
        const int bucket = b & (NBUCKET - 1);
        for (int q = 0; q < E; q++) {
            float v = gp[q] * rinv;
            gp[q] = v;
            if (q < 32) {
                atomicAdd(&g_acc[bucket][q], v);
                atomicAdd(&g_acc[bucket][32 + q], (v < 1e-5f) ? 0.f : 1.f);
            }
        }
    }
    __syncthreads();
    const size_t base = (size_t)b * D * E;
    for (int d = tid; d < D; d += blockDim.x) {
        const float* fr = f + base + (size_t)d * E;
        float acc = 0.f;
        for (int e = 0; e < E; e++) acc += fr[e] * gp[e];
        y[(size_t)b * D + d] = acc;
    }
}

extern "C" void kernel_launch(void* const* d_in, const int* in_sizes, int n_in,
                              void* d_out, int out_size) {
    const float* f    = (const float*)d_in[0];
    const float* x    = (const float*)d_in[1];
    const float* perm = (const float*)d_in[2];
    const float* gate = (const float*)d_in[3];
    const float* bias = (const float*)d_in[4];

    const int E   = in_sizes[4];
    const int DIN = in_sizes[3] / E;
    const int B   = in_sizes[1] / DIN;
    const int D   = (int)((long long)in_sizes[0] / ((long long)B * E));
    const int P   = in_sizes[2] / (E * E);
    float* y = (float*)d_out;

    const long long tail = (long long)B * D;
    const int do_tail = ((long long)out_size >= tail + 2LL * E) ? 1 : 0;

    if (E == 16 && DIN % 32 == 0 && DIN <= 512 && D % 64 == 0 && B <= MAXB) {
        int G = 888;                       // 6 CTAs/SM persistent
        if (G > B) G = B;
        if ((B + G - 1) / G > MAXROWS) G = (B + MAXROWS - 1) / MAXROWS;
        if (G > MAXG) G = MAXG;
        moe16_kernel<<<G, THREADS>>>(f, x, perm, gate, bias, y, B, D, DIN, P, do_tail);
    } else {
        init_acc_kernel<<<NBUCKET, 64>>>();
        const size_t smem = (size_t)(DIN + E * E + 2 * E + 8) * sizeof(float);
        fused_generic_kernel<<<B, THREADS, smem>>>(f, x, perm, gate, bias, y, D, DIN, P, E);
        if (do_tail)
            finalize_kernel<<<1, ((2 * E + 31) / 32) * 32>>>(y + tail, 1.f / (float)B, E);
    }
}

// round 16
// speedup vs baseline: 1.3725x; 1.3725x over previous
#include <cuda_runtime.h>
#include <cstdint>
#include <math.h>
#include <math_constants.h>

#define THREADS 256
#define NBUCKET 32
#define MAXB 32768
#define MAXG 1024
#define MAXROWS 80

__device__ float g_part[MAXG][32];   // per-block partials: [0..15] soft, [16..31] hard
__device__ int   g_ctr = 0;

// ---- fallback-path globals ----
__device__ float g_acc[NBUCKET][64];

__global__ void init_acc_kernel() {
    g_acc[blockIdx.x][threadIdx.x] = 0.f;
}

__global__ void finalize_kernel(float* __restrict__ out_tail, float invB, int E) {
    int t = threadIdx.x;
    if (t < 2 * E) {
        int idx = (t < E) ? t : (32 + (t - E));
        float s = 0.f;
        #pragma unroll
        for (int b = 0; b < NBUCKET; b++) s += g_acc[b][idx];
        out_tail[t] = s * invB;
    }
}

__device__ __forceinline__ unsigned int smem_u32(const void* p) {
    return (unsigned int)__cvta_generic_to_shared(p);
}
#define CP_ASYNC16(dst, src) \
    asm volatile("cp.async.cg.shared.global [%0], [%1], 16;" :: "r"(dst), "l"(src))
#define CP_COMMIT() asm volatile("cp.async.commit_group;")
#define CP_WAIT7()  asm volatile("cp.async.wait_group 7;" ::: "memory")

// ---------------------------------------------------------------------------
// Single fused persistent kernel. E==16, DIN%32==0, DIN<=512, D%64==0.
// Phase 2: per-warp 8-deep cp.async segment ring (smem reused from gate stage).
// ---------------------------------------------------------------------------
__global__ __launch_bounds__(THREADS) void moe16_kernel(
    const float* __restrict__ f, const float* __restrict__ x,
    const float* __restrict__ perm, const float* __restrict__ gate,
    const float* __restrict__ bias, float* __restrict__ y,
    int B, int D, int DIN, int P, int do_tail)
{
    constexpr int E = 16;
    __shared__ __align__(16) float gs[E * 513];   // phase1: gate rows; phase2: rings
    __shared__ float pw[E * E];
    __shared__ float bs[E];
    __shared__ float sgp[MAXROWS * 16];
    __shared__ float part[8][32];
    __shared__ int   last_flag;

    const int tid    = threadIdx.x;
    const int lane   = tid & 31;
    const int warpId = tid >> 5;
    const int G      = gridDim.x;
    const int nK     = DIN >> 5;

    // ---- Phase 0: stage gate / pw / bias ----
    for (int i = tid; i < E * DIN; i += THREADS) {
        int e = i / DIN, k = i - e * DIN;
        gs[e * 513 + k] = gate[i];
    }
    const float invP = 1.f / (float)P;
    for (int i = tid; i < E * E; i += THREADS) {
        float s = 0.f;
        for (int p = 0; p < P; p++) s += perm[p * E * E + i];
        pw[i] = s * invP;
    }
    if (tid < E) bs[tid] = bias[tid];
    __syncthreads();

    // ---- Phase 1: gate this block's rows (warp per row) ----
    float partial = 0.f;
    for (int idx = warpId, b = blockIdx.x + warpId * G; b < B; idx += 8, b += 8 * G) {
        const float* xr = x + (size_t)b * DIN;
        float acc[E];
        #pragma unroll
        for (int e = 0; e < E; e++) acc[e] = 0.f;

        #pragma unroll 4
        for (int i = 0; i < nK; i++) {
            const int k = lane + (i << 5);
            const float xv = xr[k];
            const float* gcol = gs + k;
            #pragma unroll
            for (int e = 0; e < E; e++) acc[e] += xv * gcol[e * 513];
        }
        #pragma unroll
        for (int off = 16; off > 0; off >>= 1) {
            #pragma unroll
            for (int e = 0; e < E; e++)
                acc[e] += __shfl_xor_sync(0xffffffffu, acc[e], off);
        }
        #pragma unroll
        for (int e = 0; e < E; e++) acc[e] += bs[e];

        float v1 = -CUDART_INF_F; int i1 = 0;
        #pragma unroll
        for (int i = 0; i < E; i++) if (acc[i] > v1) { v1 = acc[i]; i1 = i; }
        float v2 = -CUDART_INF_F; int i2 = 0;
        #pragma unroll
        for (int i = 0; i < E; i++) if (i != i1 && acc[i] > v2) { v2 = acc[i]; i2 = i; }
        float m1 = (v1 == 0.f) ? -CUDART_INF_F : v1;
        float m2 = (v2 == 0.f) ? -CUDART_INF_F : v2;
        float m  = fmaxf(m1, m2);
        float e1 = __expf(m1 - m), e2 = __expf(m2 - m);
        float zi = 1.f / (e1 + e2);
        float g1 = e1 * zi, g2 = e2 * zi;
        float raw[E]; float s = 0.f;
        #pragma unroll
        for (int q = 0; q < E; q++) {
            raw[q] = g1 * pw[i1 * E + q] + g2 * pw[i2 * E + q];
            s += raw[q];
        }
        const float rinv = 1.f / s;

        const float val = raw[lane & 15] * rinv;
        if (lane < 16) {
            sgp[idx * 16 + lane] = val;
            partial += val;
        } else {
            partial += (val < 1e-5f) ? 0.f : 1.f;
        }
    }
    part[warpId][lane] = partial;
    __syncthreads();    // also separates gs reads (phase 1) from ring writes (phase 2)
    if (tid < 32) {
        float s = 0.f;
        #pragma unroll
        for (int w = 0; w < 8; w++) s += part[w][tid];
        g_part[blockIdx.x][tid] = s;
    }

    // ---- Phase 2: stream rows via 8-deep cp.async segment ring per warp ----
    {
        const int segPerRow = D >> 6;                 // 512B segments per warp per row
        const int nrows = (blockIdx.x < B) ? ((B - 1 - blockIdx.x) / G + 1) : 0;
        const long total = (long)nrows * segPerRow;
        float4* ring = ((float4*)gs) + warpId * 256;  // 8 slots x 32 float4 = 4KB
        const unsigned int ringAddr = smem_u32(ring) + (unsigned int)lane * 16u;
        const int dPerWarp = D >> 3;
        const int outLane = lane >> 2;
        const bool qlead = (lane & 3) == 0;

        const size_t rowStride4 = (size_t)D * 4;      // float4s per f row
        const size_t rowStep4   = (size_t)G * rowStride4;
        const float4* lsrc = (const float4*)f + (size_t)blockIdx.x * rowStride4
                             + (size_t)warpId * (D >> 1) + lane;
        int lj = 0;
        long s = 0;
        const long pro = (total < 8) ? total : 8;
        for (; s < pro; ++s) {
            CP_ASYNC16(ringAddr + (unsigned int)((s & 7) * 512), (const void*)(lsrc + (size_t)lj * 32));
            CP_COMMIT();
            if (++lj == segPerRow) { lj = 0; lsrc += rowStep4; }
        }
        for (long q = pro; q < 8; ++q) CP_COMMIT();   // pad pending to 8

        int cr = 0, cj = 0;
        float4 wsel = make_float4(0.f, 0.f, 0.f, 0.f);
        float* yr = y;
        if (total > 0) {
            wsel = ((const float4*)sgp)[lane & 3];
            yr = y + (size_t)blockIdx.x * D + warpId * dPerWarp;
        }
        for (long c = 0; c < total; ++c) {
            CP_WAIT7();                               // group c complete
            float4 a = ring[(c & 7) * 32 + lane];     // LDS.128, conflict-free
            float p = a.x * wsel.x + a.y * wsel.y + a.z * wsel.z + a.w * wsel.w;
            p += __shfl_xor_sync(0xffffffffu, p, 1);
            p += __shfl_xor_sync(0xffffffffu, p, 2);
            if (qlead) yr[cj * 8 + outLane] = p;
            if (s < total) {
                CP_ASYNC16(ringAddr + (unsigned int)((s & 7) * 512), (const void*)(lsrc + (size_t)lj * 32));
                if (++lj == segPerRow) { lj = 0; lsrc += rowStep4; }
                ++s;
            }
            CP_COMMIT();                              // real or empty: pending stays 8
            if (++cj == segPerRow) {
                cj = 0; ++cr;
                if (cr < nrows) {
                    wsel = ((const float4*)(sgp + cr * 16))[lane & 3];
                    yr = y + ((size_t)blockIdx.x + (size_t)cr * G) * D + warpId * dPerWarp;
                }
            }
        }
        asm volatile("cp.async.wait_all;" ::: "memory");
    }

    // ---- Phase 3: last block reduces partials, writes tail ----
    __syncthreads();
    if (tid == 0) {
        __threadfence();
        int old = atomicAdd(&g_ctr, 1);
        last_flag = (old == G - 1) ? 1 : 0;
    }
    __syncthreads();
    if (last_flag) {
        __threadfence();
        float s = 0.f;
        for (int i = warpId; i < G; i += 8) s += g_part[i][lane];
        part[warpId][lane] = s;
        __syncthreads();
        if (tid < 32) {
            float tot = 0.f;
            #pragma unroll
            for (int w = 0; w < 8; w++) tot += part[w][tid];
            if (do_tail)
                y[(size_t)B * D + tid] = tot / (float)B;
        }
        if (tid == 0) g_ctr = 0;
    }
}

// ---------------------------------------------------------------------------
// Generic fallback (any E <= 32)
// ---------------------------------------------------------------------------
__global__ void fused_generic_kernel(
    const float* __restrict__ f, const float* __restrict__ x,
    const float* __restrict__ perm, const float* __restrict__ gate,
    const float* __restrict__ bias, float* __restrict__ y,
    int D, int DIN, int P, int E)
{
    extern __shared__ float smem[];
    float* xs     = smem;
    float* pw     = xs + DIN;
    float* logits = pw + E * E;
    float* gp     = logits + E;
    const int tid = threadIdx.x;
    const int b   = blockIdx.x;

    for (int k = tid; k < DIN; k += blockDim.x) xs[k] = x[(size_t)b * DIN + k];
    const float invP = 1.f / (float)P;
    for (int i = tid; i < E * E; i += blockDim.x) {
        float s = 0.f;
        for (int p = 0; p < P; p++) s += perm[p * E * E + i];
        pw[i] = s * invP;
    }
    __syncthreads();
    for (int e = tid; e < E; e += blockDim.x) {
        float s = 0.f;
        const float* gr = gate + (size_t)e * DIN;
        for (int k = 0; k < DIN; k++) s += xs[k] * gr[k];
        logits[e] = s + bias[e];
    }
    __syncthreads();
    if (tid == 0) {
        float v1 = -CUDART_INF_F; int i1 = 0;
        for (int i = 0; i < E; i++) if (logits[i] > v1) { v1 = logits[i]; i1 = i; }
        float v2 = -CUDART_INF_F; int i2 = 0;
        for (int i = 0; i < E; i++) if (i != i1 && logits[i] > v2) { v2 = logits[i]; i2 = i; }
        float m1 = (v1 == 0.f) ? -CUDART_INF_F : v1;
        float m2 = (v2 == 0.f) ? -CUDART_INF_F : v2;
        float m  = fmaxf(m1, m2);
        float e1 = __expf(m1 - m), e2 = __expf(m2 - m);
        float zi = 1.f / (e1 + e2);
        float g1 = e1 * zi, g2 = e2 * zi;
        float s = 0.f;
        for (int q = 0; q < E; q++) {
            float r = g1 * pw[i1 * E + q] + g2 * pw[i2 * E + q];
            gp[q] = r; s += r;
        }
        const float rinv = 1.f / s;
        const int bucket = b & (NBUCKET - 1);
        for (int q = 0; q < E; q++) {
            float v = gp[q] * rinv;
            gp[q] = v;
            if (q < 32) {
                atomicAdd(&g_acc[bucket][q], v);
                atomicAdd(&g_acc[bucket][32 + q], (v < 1e-5f) ? 0.f : 1.f);
            }
        }
    }
    __syncthreads();
    const size_t base = (size_t)b * D * E;
    for (int d = tid; d < D; d += blockDim.x) {
        const float* fr = f + base + (size_t)d * E;
        float acc = 0.f;
        for (int e = 0; e < E; e++) acc += fr[e] * gp[e];
        y[(size_t)b * D + d] = acc;
    }
}

extern "C" void kernel_launch(void* const* d_in, const int* in_sizes, int n_in,
                              void* d_out, int out_size) {
    const float* f    = (const float*)d_in[0];
    const float* x    = (const float*)d_in[1];
    const float* perm = (const float*)d_in[2];
    const float* gate = (const float*)d_in[3];
    const float* bias = (const float*)d_in[4];

    const int E   = in_sizes[4];
    const int DIN = in_sizes[3] / E;
    const int B   = in_sizes[1] / DIN;
    const int D   = (int)((long long)in_sizes[0] / ((long long)B * E));
    const int P   = in_sizes[2] / (E * E);
    float* y = (float*)d_out;

    const long long tail = (long long)B * D;
    const int do_tail = ((long long)out_size >= tail + 2LL * E) ? 1 : 0;

    if (E == 16 && DIN % 32 == 0 && DIN <= 512 && D % 64 == 0 && B <= MAXB) {
        int G = 592;                       // 4 CTAs/SM persistent (R11-proven)
        if (G > B) G = B;
        if ((B + G - 1) / G > MAXROWS) G = (B + MAXROWS - 1) / MAXROWS;
        if (G > MAXG) G = MAXG;
        moe16_kernel<<<G, THREADS>>>(f, x, perm, gate, bias, y, B, D, DIN, P, do_tail);
    } else {
        init_acc_kernel<<<NBUCKET, 64>>>();
        const size_t smem = (size_t)(DIN + E * E + 2 * E + 8) * sizeof(float);
        fused_generic_kernel<<<B, THREADS, smem>>>(f, x, perm, gate, bias, y, D, DIN, P, E);
        if (do_tail)
            finalize_kernel<<<1, ((2 * E + 31) / 32) * 32>>>(y + tail, 1.f / (float)B, E);
    }
}

// round 17
// speedup vs baseline: 1.4176x; 1.0329x over previous
#include <cuda_runtime.h>
#include <cstdint>
#include <math.h>
#include <math_constants.h>

#define THREADS 256
#define NBUCKET 32
#define MAXB 32768
#define MAXG 1024
#define MAXROWS 80

__device__ float g_part[MAXG][32];   // per-block partials: [0..15] soft, [16..31] hard
__device__ int   g_ctr = 0;

// ---- fallback-path globals ----
__device__ float g_acc[NBUCKET][64];

__global__ void init_acc_kernel() {
    g_acc[blockIdx.x][threadIdx.x] = 0.f;
}

__global__ void finalize_kernel(float* __restrict__ out_tail, float invB, int E) {
    int t = threadIdx.x;
    if (t < 2 * E) {
        int idx = (t < E) ? t : (32 + (t - E));
        float s = 0.f;
        #pragma unroll
        for (int b = 0; b < NBUCKET; b++) s += g_acc[b][idx];
        out_tail[t] = s * invB;
    }
}

// ---------------------------------------------------------------------------
// Single fused persistent kernel. E==16, DIN%32==0, DIN<=512, D==512.
// Phase 2: register double-buffered half-row pipeline (2KB always in flight).
// ---------------------------------------------------------------------------
__global__ __launch_bounds__(THREADS) void moe16_kernel(
    const float* __restrict__ f, const float* __restrict__ x,
    const float* __restrict__ perm, const float* __restrict__ gate,
    const float* __restrict__ bias, float* __restrict__ y,
    int B, int D, int DIN, int P, int do_tail)
{
    constexpr int E = 16;
    __shared__ __align__(16) float gs[E * 513];
    __shared__ float pw[E * E];
    __shared__ float bs[E];
    __shared__ __align__(16) float sgp[MAXROWS * 16];
    __shared__ float part[8][32];
    __shared__ int   last_flag;

    const int tid    = threadIdx.x;
    const int lane   = tid & 31;
    const int warpId = tid >> 5;
    const int G      = gridDim.x;
    const int nK     = DIN >> 5;

    // ---- Phase 0: stage gate / pw / bias ----
    for (int i = tid; i < E * DIN; i += THREADS) {
        int e = i / DIN, k = i - e * DIN;
        gs[e * 513 + k] = gate[i];
    }
    const float invP = 1.f / (float)P;
    for (int i = tid; i < E * E; i += THREADS) {
        float s = 0.f;
        for (int p = 0; p < P; p++) s += perm[p * E * E + i];
        pw[i] = s * invP;
    }
    if (tid < E) bs[tid] = bias[tid];
    __syncthreads();

    // ---- Phase 1: gate this block's rows (warp per row) ----
    float partial = 0.f;
    for (int idx = warpId, b = blockIdx.x + warpId * G; b < B; idx += 8, b += 8 * G) {
        const float* xr = x + (size_t)b * DIN;
        float acc[E];
        #pragma unroll
        for (int e = 0; e < E; e++) acc[e] = 0.f;

        #pragma unroll 4
        for (int i = 0; i < nK; i++) {
            const int k = lane + (i << 5);
            const float xv = xr[k];
            const float* gcol = gs + k;
            #pragma unroll
            for (int e = 0; e < E; e++) acc[e] += xv * gcol[e * 513];
        }
        #pragma unroll
        for (int off = 16; off > 0; off >>= 1) {
            #pragma unroll
            for (int e = 0; e < E; e++)
                acc[e] += __shfl_xor_sync(0xffffffffu, acc[e], off);
        }
        #pragma unroll
        for (int e = 0; e < E; e++) acc[e] += bs[e];

        float v1 = -CUDART_INF_F; int i1 = 0;
        #pragma unroll
        for (int i = 0; i < E; i++) if (acc[i] > v1) { v1 = acc[i]; i1 = i; }
        float v2 = -CUDART_INF_F; int i2 = 0;
        #pragma unroll
        for (int i = 0; i < E; i++) if (i != i1 && acc[i] > v2) { v2 = acc[i]; i2 = i; }
        float m1 = (v1 == 0.f) ? -CUDART_INF_F : v1;
        float m2 = (v2 == 0.f) ? -CUDART_INF_F : v2;
        float m  = fmaxf(m1, m2);
        float e1 = __expf(m1 - m), e2 = __expf(m2 - m);
        float zi = 1.f / (e1 + e2);
        float g1 = e1 * zi, g2 = e2 * zi;
        float raw[E]; float s = 0.f;
        #pragma unroll
        for (int q = 0; q < E; q++) {
            raw[q] = g1 * pw[i1 * E + q] + g2 * pw[i2 * E + q];
            s += raw[q];
        }
        const float rinv = 1.f / s;

        const float val = raw[lane & 15] * rinv;
        if (lane < 16) {
            sgp[idx * 16 + lane] = val;
            partial += val;
        } else {
            partial += (val < 1e-5f) ? 0.f : 1.f;
        }
    }
    part[warpId][lane] = partial;
    __syncthreads();
    if (tid < 32) {
        float s = 0.f;
        #pragma unroll
        for (int w = 0; w < 8; w++) s += part[w][tid];
        g_part[blockIdx.x][tid] = s;
    }

    // ---- Phase 2: stream rows. D==512. Half-row (2KB/warp) double-buffer:
    //      issue(next) always precedes consume(cur) -> loads never drain.
    {
        const int bid = (int)blockIdx.x;
        const int nrows = (B - 1 - bid) / G + 1;     // >= 1 since G <= B
        const int total = nrows * 2;                 // two 2KB halves per row
        const float4* f4 = (const float4*)f + (size_t)warpId * 256 + lane;
        const float4* wq = (const float4*)sgp;
        const int wsub = lane & 3;
        const int outLane = lane >> 2;
        const bool qlead = (wsub == 0);
        float* ybase = y + (size_t)warpId * 64;

        float4 a0, a1, a2, a3, b0, b1, b2, b3;

#define MOE_ISSUE(v0, v1, v2, v3, i) do {                                     \
    int _r = (i) >> 1, _p = (i) & 1;                                          \
    const float4* _s = f4 + ((size_t)bid + (size_t)_r * G) * 2048 + _p * 128; \
    v0 = _s[0]; v1 = _s[32]; v2 = _s[64]; v3 = _s[96];                        \
} while (0)

#define MOE_CONS(v0, v1, v2, v3, i) do {                                      \
    int _r = (i) >> 1, _p = (i) & 1;                                          \
    float4 _w = wq[_r * 4 + wsub];                                            \
    float* _yr = ybase + ((size_t)bid + (size_t)_r * G) * 512 + _p * 32;      \
    float p0 = v0.x*_w.x + v0.y*_w.y + v0.z*_w.z + v0.w*_w.w;                 \
    float p1 = v1.x*_w.x + v1.y*_w.y + v1.z*_w.z + v1.w*_w.w;                 \
    float p2 = v2.x*_w.x + v2.y*_w.y + v2.z*_w.z + v2.w*_w.w;                 \
    float p3 = v3.x*_w.x + v3.y*_w.y + v3.z*_w.z + v3.w*_w.w;                 \
    p0 += __shfl_xor_sync(0xffffffffu, p0, 1);                                \
    p1 += __shfl_xor_sync(0xffffffffu, p1, 1);                                \
    p2 += __shfl_xor_sync(0xffffffffu, p2, 1);                                \
    p3 += __shfl_xor_sync(0xffffffffu, p3, 1);                                \
    p0 += __shfl_xor_sync(0xffffffffu, p0, 2);                                \
    p1 += __shfl_xor_sync(0xffffffffu, p1, 2);                                \
    p2 += __shfl_xor_sync(0xffffffffu, p2, 2);                                \
    p3 += __shfl_xor_sync(0xffffffffu, p3, 2);                                \
    if (qlead) {                                                              \
        _yr[outLane]      = p0; _yr[8  + outLane] = p1;                       \
        _yr[16 + outLane] = p2; _yr[24 + outLane] = p3;                       \
    }                                                                         \
} while (0)

        MOE_ISSUE(a0, a1, a2, a3, 0);
        int i = 0;
        for (; i + 2 < total; i += 2) {
            MOE_ISSUE(b0, b1, b2, b3, i + 1);
            MOE_CONS (a0, a1, a2, a3, i);
            MOE_ISSUE(a0, a1, a2, a3, i + 2);
            MOE_CONS (b0, b1, b2, b3, i + 1);
        }
        MOE_ISSUE(b0, b1, b2, b3, i + 1);
        MOE_CONS (a0, a1, a2, a3, i);
        MOE_CONS (b0, b1, b2, b3, i + 1);
#undef MOE_ISSUE
#undef MOE_CONS
    }

    // ---- Phase 3: last block reduces partials, writes tail ----
    __syncthreads();
    if (tid == 0) {
        __threadfence();
        int old = atomicAdd(&g_ctr, 1);
        last_flag = (old == G - 1) ? 1 : 0;
    }
    __syncthreads();
    if (last_flag) {
        __threadfence();
        float s = 0.f;
        for (int i = warpId; i < G; i += 8) s += g_part[i][lane];
        part[warpId][lane] = s;
        __syncthreads();
        if (tid < 32) {
            float tot = 0.f;
            #pragma unroll
            for (int w = 0; w < 8; w++) tot += part[w][tid];
            if (do_tail)
                y[(size_t)B * D + tid] = tot / (float)B;
        }
        if (tid == 0) g_ctr = 0;
    }
}

// ---------------------------------------------------------------------------
// Generic fallback (any E <= 32)
// ---------------------------------------------------------------------------
__global__ void fused_generic_kernel(
    const float* __restrict__ f, const float* __restrict__ x,
    const float* __restrict__ perm, const float* __restrict__ gate,
    const float* __restrict__ bias, float* __restrict__ y,
    int D, int DIN, int P, int E)
{
    extern __shared__ float smem[];
    float* xs     = smem;
    float* pw     = xs + DIN;
    float* logits = pw + E * E;
    float* gp     = logits + E;
    const int tid = threadIdx.x;
    const int b   = blockIdx.x;

    for (int k = tid; k < DIN; k += blockDim.x) xs[k] = x[(size_t)b * DIN + k];
    const float invP = 1.f / (float)P;
    for (int i = tid; i < E * E; i += blockDim.x) {
        float s = 0.f;
        for (int p = 0; p < P; p++) s += perm[p * E * E + i];
        pw[i] = s * invP;
    }
    __syncthreads();
    for (int e = tid; e < E; e += blockDim.x) {
        float s = 0.f;
        const float* gr = gate + (size_t)e * DIN;
        for (int k = 0; k < DIN; k++) s += xs[k] * gr[k];
        logits[e] = s + bias[e];
    }
    __syncthreads();
    if (tid == 0) {
        float v1 = -CUDART_INF_F; int i1 = 0;
        for (int i = 0; i < E; i++) if (logits[i] > v1) { v1 = logits[i]; i1 = i; }
        float v2 = -CUDART_INF_F; int i2 = 0;
        for (int i = 0; i < E; i++) if (i != i1 && logits[i] > v2) { v2 = logits[i]; i2 = i; }
        float m1 = (v1 == 0.f) ? -CUDART_INF_F : v1;
        float m2 = (v2 == 0.f) ? -CUDART_INF_F : v2;
        float m  = fmaxf(m1, m2);
        float e1 = __expf(m1 - m), e2 = __expf(m2 - m);
        float zi = 1.f / (e1 + e2);
        float g1 = e1 * zi, g2 = e2 * zi;
        float s = 0.f;
        for (int q = 0; q < E; q++) {
            float r = g1 * pw[i1 * E + q] + g2 * pw[i2 * E + q];
            gp[q] = r; s += r;
        }
        const float rinv = 1.f / s;
        const int bucket = b & (NBUCKET - 1);
        for (int q = 0; q < E; q++) {
            float v = gp[q] * rinv;
            gp[q] = v;
            if (q < 32) {
                atomicAdd(&g_acc[bucket][q], v);
                atomicAdd(&g_acc[bucket][32 + q], (v < 1e-5f) ? 0.f : 1.f);
            }
        }
    }
    __syncthreads();
    const size_t base = (size_t)b * D * E;
    for (int d = tid; d < D; d += blockDim.x) {
        const float* fr = f + base + (size_t)d * E;
        float acc = 0.f;
        for (int e = 0; e < E; e++) acc += fr[e] * gp[e];
        y[(size_t)b * D + d] = acc;
    }
}

extern "C" void kernel_launch(void* const* d_in, const int* in_sizes, int n_in,
                              void* d_out, int out_size) {
    const float* f    = (const float*)d_in[0];
    const float* x    = (const float*)d_in[1];
    const float* perm = (const float*)d_in[2];
    const float* gate = (const float*)d_in[3];
    const float* bias = (const float*)d_in[4];

    const int E   = in_sizes[4];
    const int DIN = in_sizes[3] / E;
    const int B   = in_sizes[1] / DIN;
    const int D   = (int)((long long)in_sizes[0] / ((long long)B * E));
    const int P   = in_sizes[2] / (E * E);
    float* y = (float*)d_out;

    const long long tail = (long long)B * D;
    const int do_tail = ((long long)out_size >= tail + 2LL * E) ? 1 : 0;

    if (E == 16 && DIN % 32 == 0 && DIN <= 512 && D == 512 && B <= MAXB) {
        int G = 592;                       // 4 CTAs/SM persistent (R11-proven)
        if (G > B) G = B;
        if ((B + G - 1) / G > MAXROWS) G = (B + MAXROWS - 1) / MAXROWS;
        if (G > MAXG) G = MAXG;
        moe16_kernel<<<G, THREADS>>>(f, x, perm, gate, bias, y, B, D, DIN, P, do_tail);
    } else {
        init_acc_kernel<<<NBUCKET, 64>>>();
        const size_t smem = (size_t)(DIN + E * E + 2 * E + 8) * sizeof(float);
        fused_generic_kernel<<<B, THREADS, smem>>>(f, x, perm, gate, bias, y, D, DIN, P, E);
        if (do_tail)
            finalize_kernel<<<1, ((2 * E + 31) / 32) * 32>>>(y + tail, 1.f / (float)B, E);
    }
}